// round 15
// baseline (speedup 1.0000x reference)
#include <cuda_runtime.h>

typedef unsigned long long u64;

#define NB 1024
#define SL 512
#define NL 64

__device__ __forceinline__ u64 fma2(u64 a, u64 b, u64 c) {
    u64 d;
    asm("fma.rn.f32x2 %0, %1, %2, %3;" : "=l"(d) : "l"(a), "l"(b), "l"(c));
    return d;
}
__device__ __forceinline__ u64 add2(u64 a, u64 b) {
    u64 d;
    asm("add.rn.f32x2 %0, %1, %2;" : "=l"(d) : "l"(a), "l"(b));
    return d;
}
__device__ __forceinline__ u64 pack2(float lo, float hi) {
    u64 d;
    asm("mov.b64 %0, {%1, %2};" : "=l"(d) : "f"(lo), "f"(hi));
    return d;
}
__device__ __forceinline__ void unpack2(u64 a, float& lo, float& hi) {
    asm("mov.b64 {%0, %1}, %2;" : "=f"(lo), "=f"(hi) : "l"(a));
}

// MUFU-free exp2 (proven R11): magic round + deg-4 Taylor + exponent splice.
__device__ __forceinline__ float fexp2(float t) {
    const float MAGIC = 12582912.0f;            // 1.5 * 2^23
    const float r  = t + MAGIC;
    const float fn = r - MAGIC;
    const float f  = t - fn;
    float p = 0.0096181f;
    p = fmaf(p, f, 0.0555042f);
    p = fmaf(p, f, 0.2402265f);
    p = fmaf(p, f, 0.6931472f);
    p = fmaf(p, f, 1.0f);
    return __uint_as_float(__float_as_uint(p) + (__float_as_uint(r) << 23));
}

// ROW-SPLIT shape: 64-thread block = 1 batch, TWO warps per batch
// (13.8 warps/SM = 3.46/SMSP of latency hiding — R14 was stuck at 1.73).
// Warp w computes partials for ALL 64 columns over rows [32w, 32w+32):
// per warp only 8 LDS.128 + 32 fma2 per step (HALF of R14's stream each).
// Lane l produces partials for cols (2l, 2l+1); after the exchange,
// thread t combines column t (one fexp2 per thread). Two __syncthreads
// per step, hidden by the doubled warp count.
// Math proven in R11/R13: log2-domain multiplicative recurrence (exact for
// any scalar C2), per-step re-anchor via guarded smem scalar, branchless
// selects, x4 time-unroll with MLP=5 group prefetch.
#define STEP(PB, CBF, E2, MK, E2N) do {                                       \
    __syncthreads();                                                           \
    const float C2 = csm[(PB)];                                                \
    const float cf = fexp2((E2) - C2);                                         \
    const ulonglong2* qp = (const ulonglong2*)(qbuf[(PB)] + 32 * w);           \
    u64 A0 = 0, A1 = 0, B0 = 0, B1 = 0;                                        \
    _Pragma("unroll")                                                          \
    for (int k = 0; k < 4; k++) {                                              \
        ulonglong2 v0 = qp[2 * k];                                             \
        ulonglong2 v1 = qp[2 * k + 1];                                         \
        A0 = fma2(v0.x, Ea[4 * k + 0], A0);  B0 = fma2(v0.x, Eb[4 * k + 0], B0);\
        A1 = fma2(v0.y, Ea[4 * k + 1], A1);  B1 = fma2(v0.y, Eb[4 * k + 1], B1);\
        A0 = fma2(v1.x, Ea[4 * k + 2], A0);  B0 = fma2(v1.x, Eb[4 * k + 2], B0);\
        A1 = fma2(v1.y, Ea[4 * k + 3], A1);  B1 = fma2(v1.y, Eb[4 * k + 3], B1);\
    }                                                                          \
    float xa, ya, xb, yb;                                                      \
    unpack2(add2(A0, A1), xa, ya);                                             \
    unpack2(add2(B0, B1), xb, yb);                                             \
    *(float2*)&part[w][2 * l] = make_float2(xa + ya, xb + yb);                 \
    __syncthreads();                                                           \
    const float s = part[0][j] + part[1][j];                                   \
    q  = (MK) ? s * cf  : q;                                                   \
    Z2 = (MK) ? Z2 + C2 : Z2;                                                  \
    qbuf[(CBF)][j] = q;                                                        \
    const int nn = (int)(__float_as_uint(q) >> 23) - 127;                      \
    const float Cn = (float)nn + (E2N);                                        \
    if (tid == 0) csm[(CBF)] = Cn;                                             \
} while (0)

__global__ __launch_bounds__(64) void crf_fwd_kernel(
    const float* __restrict__ emissions,
    const int*   __restrict__ mask,
    const float* __restrict__ trans,
    const float* __restrict__ startt,
    const float* __restrict__ endt,
    float* __restrict__ out)
{
    __shared__ __align__(16) float qbuf[2][NL];
    __shared__ __align__(8)  float part[2][NL];
    __shared__ float csm[2];
    __shared__ float red[2];

    const int tid = threadIdx.x;
    const int w   = tid >> 5;
    const int l   = tid & 31;
    const int b   = blockIdx.x;
    const int j   = tid;                       // combine column
    const float* ep = emissions + (size_t)b * SL * NL + j;   // ep[t*NL]
    const int*   mp = mask + b * SL;
    const unsigned FULL = 0xffffffffu;
    const float LN2 = 0.6931471805599453f;
    const float L2E = 1.4426950408889634f;

    // E for partial cols (2l, 2l+1) over this warp's rows [32w, 32w+32),
    // packed over adjacent row pairs to match the ulonglong2 q reads.
    const int ca = 2 * l, cb = 2 * l + 1;
    u64 Ea[16], Eb[16];
#pragma unroll
    for (int m = 0; m < 16; m++) {
        const int r = 32 * w + 2 * m;
        Ea[m] = pack2(__expf(trans[r * NL + ca]), __expf(trans[(r + 1) * NL + ca]));
        Eb[m] = pack2(__expf(trans[r * NL + cb]), __expf(trans[(r + 1) * NL + cb]));
    }
    const float fend = __expf(endt[j]);

    // t = 0: normalize by score_0 -> q_0 = 1 exactly (one-time MUFU ok).
    const float sc = startt[j] + ep[0];
    if (tid == 0) red[0] = sc;
    __syncthreads();
    const float z0 = red[0];
    float q  = __expf(sc - z0);
    float Z2 = z0 * L2E;                        // log2-domain accumulator
    qbuf[0][j] = q;

    // prefetch t = 1..7 (log2-scaled) + masks, MLP ~ 9
    float e1 = L2E * ep[(size_t)1 * NL];
    float e2 = L2E * ep[(size_t)2 * NL];
    float e3 = L2E * ep[(size_t)3 * NL];
    float g0 = L2E * ep[(size_t)4 * NL];
    float g1 = L2E * ep[(size_t)5 * NL];
    float g2 = L2E * ep[(size_t)6 * NL];
    float g3 = L2E * ep[(size_t)7 * NL];
    const int4 m0 = *(const int4*)mp;           // .y,.z,.w -> t = 1,2,3
    int4 mv = *(const int4*)(mp + 4);           // t = 4..7

    if (tid == 0) csm[0] = e1;                  // C2_1 = e2_0^1 (q_0 = 1)

    // prologue: t = 1..3
    STEP(0, 1, e1, m0.y, e2);
    STEP(1, 0, e2, m0.z, e3);
    STEP(0, 1, e3, m0.w, g0);

    // main loop: groups of 4, next group prefetched at group top (MLP = 5)
#pragma unroll 1
    for (int t0 = 4; t0 < SL; t0 += 4) {
        const int tn0 = (t0 + 4 < SL) ? t0 + 4 : SL - 4;    // clamped reload ok
        const float n0 = L2E * ep[(size_t)(tn0    ) * NL];
        const float n1 = L2E * ep[(size_t)(tn0 + 1) * NL];
        const float n2 = L2E * ep[(size_t)(tn0 + 2) * NL];
        const float n3 = L2E * ep[(size_t)(tn0 + 3) * NL];
        const int4 nmv = *(const int4*)(mp + tn0);

        STEP(1, 0, g0, mv.x, g1);
        STEP(0, 1, g1, mv.y, g2);
        STEP(1, 0, g2, mv.z, g3);
        STEP(0, 1, g3, mv.w, n0);

        g0 = n0; g1 = n1; g2 = n2; g3 = n3; mv = nmv;
    }

    // out[b] = Z2*ln2 + ln( sum_j q_j * exp(end_j) )
    float v = q * fend;
#pragma unroll
    for (int o = 16; o; o >>= 1) v += __shfl_xor_sync(FULL, v, o);
    if (l == 0) red[w] = v;
    __syncthreads();
    if (tid == 0) out[b] = fmaf(Z2, LN2, __logf(red[0] + red[1]));
}

extern "C" void kernel_launch(void* const* d_in, const int* in_sizes, int n_in,
                              void* d_out, int out_size) {
    const float* emissions = (const float*)d_in[0];
    const int*   msk       = (const int*)d_in[1];
    const float* trans     = (const float*)d_in[2];
    const float* startt    = (const float*)d_in[3];
    const float* endt      = (const float*)d_in[4];
    crf_fwd_kernel<<<NB, NL>>>(emissions, msk, trans, startt, endt, (float*)d_out);
}

// round 17
// speedup vs baseline: 1.1354x; 1.1354x over previous
#include <cuda_runtime.h>

typedef unsigned long long u64;
typedef unsigned int u32;

#define NB 1024
#define SL 512
#define NL 64

__device__ __forceinline__ u64 fma2(u64 a, u64 b, u64 c) {
    u64 d;
    asm("fma.rn.f32x2 %0, %1, %2, %3;" : "=l"(d) : "l"(a), "l"(b), "l"(c));
    return d;
}
__device__ __forceinline__ u64 add2(u64 a, u64 b) {
    u64 d;
    asm("add.rn.f32x2 %0, %1, %2;" : "=l"(d) : "l"(a), "l"(b));
    return d;
}
__device__ __forceinline__ u64 mul2(u64 a, u64 b) {
    u64 d;
    asm("mul.rn.f32x2 %0, %1, %2;" : "=l"(d) : "l"(a), "l"(b));
    return d;
}
__device__ __forceinline__ u64 pack2(float lo, float hi) {
    u64 d;
    asm("mov.b64 %0, {%1, %2};" : "=l"(d) : "f"(lo), "f"(hi));
    return d;
}
__device__ __forceinline__ void unpack2(u64 a, float& lo, float& hi) {
    asm("mov.b64 {%0, %1}, %2;" : "=f"(lo), "=f"(hi) : "l"(a));
}
__device__ __forceinline__ void unpacku(u64 a, u32& lo, u32& hi) {
    asm("mov.b64 {%0, %1}, %2;" : "=r"(lo), "=r"(hi) : "l"(a));
}

// R14 champion (148us) with the exp path VECTORIZED: both per-lane exp2's
// computed as ONE packed f32x2 pipeline (8 fma2 vs 16 scalar fma-class),
// per-half exponent splice on the alu pipe. Emissions stay packed from the
// load (single mul2 by log2e). ~10 fewer issue slots per warp-step on a
// 115-instr stream that runs at ~2 cyc/instr effective.
// Everything else identical: 128-thread CTA = 4 independent warps = 4
// batches; lane l owns columns (2l, 2l+1); 16 LDS.128 + 64 fma2 per step;
// log2-domain multiplicative recurrence (exact for any scalar C2); per-step
// re-anchored normalizer; x4 time-unroll with MLP=5 group prefetch; selects.
#define STEP(PB, CBF, EM2, MK) do {                                          \
    __syncwarp(FULL);                                                          \
    /* packed exp2(em - C2) for both columns */                               \
    const u64 t2  = fma2(C2p, NEG1, (EM2));                                    \
    const u64 r2  = add2(t2, MAG2);                                            \
    const u64 fn2 = fma2(MAG2, NEG1, r2);                                      \
    const u64 f2  = fma2(fn2, NEG1, t2);                                       \
    u64 p2 = fma2(P4, f2, P3);                                                 \
    p2 = fma2(p2, f2, P2);                                                     \
    p2 = fma2(p2, f2, P1);                                                     \
    p2 = fma2(p2, f2, ONE2);                                                   \
    u32 rlo, rhi, plo, phi;                                                    \
    unpacku(r2, rlo, rhi);                                                     \
    unpacku(p2, plo, phi);                                                     \
    const float cfa = __uint_as_float(plo + (rlo << 23));                      \
    const float cfb = __uint_as_float(phi + (rhi << 23));                      \
    const ulonglong2* qp = (const ulonglong2*)qbuf[w][(PB)];                   \
    u64 a0 = 0, a1 = 0, c0 = 0, c1 = 0;                                        \
    _Pragma("unroll")                                                          \
    for (int k = 0; k < 8; k++) {                                              \
        ulonglong2 v0 = qp[2 * k];                                             \
        ulonglong2 v1 = qp[2 * k + 1];                                         \
        a0 = fma2(v0.x, Ea[4 * k + 0], a0);  c0 = fma2(v0.x, Eb[4 * k + 0], c0);\
        a1 = fma2(v0.y, Ea[4 * k + 1], a1);  c1 = fma2(v0.y, Eb[4 * k + 1], c1);\
        a0 = fma2(v1.x, Ea[4 * k + 2], a0);  c0 = fma2(v1.x, Eb[4 * k + 2], c0);\
        a1 = fma2(v1.y, Ea[4 * k + 3], a1);  c1 = fma2(v1.y, Eb[4 * k + 3], c1);\
    }                                                                          \
    float xa, ya, xb, yb;                                                      \
    unpack2(add2(a0, a1), xa, ya);                                             \
    unpack2(add2(c0, c1), xb, yb);                                             \
    const float sa = xa + ya;                                                  \
    const float sb = xb + yb;                                                  \
    qa = (MK) ? sa * cfa : qa;                                                 \
    qb = (MK) ? sb * cfb : qb;                                                 \
    Z2 = (MK) ? Z2 + C2  : Z2;                                                 \
    *(float2*)&qbuf[w][(CBF)][ca] = make_float2(qa, qb);                       \
} while (0)

// re-anchor: C2' = exponent(q_0) + e2_0^{next}; lane-0 broadcast; repack.
#define CUPD(NEXT_EM2) do {                                                   \
    float nlo, nhi;                                                            \
    unpack2((NEXT_EM2), nlo, nhi);                                             \
    const int n = (int)(__float_as_uint(qa) >> 23) - 127;                      \
    C2  = __shfl_sync(FULL, (float)n + nlo, 0);                                \
    C2p = pack2(C2, C2);                                                       \
} while (0)

__global__ __launch_bounds__(128) void crf_fwd_kernel(
    const float* __restrict__ emissions,
    const int*   __restrict__ mask,
    const float* __restrict__ trans,
    const float* __restrict__ startt,
    const float* __restrict__ endt,
    float* __restrict__ out)
{
    __shared__ __align__(16) float qbuf[4][2][NL];   // [warp][buf][label]

    const int tid = threadIdx.x;
    const int w   = tid >> 5;
    const int l   = tid & 31;
    const int b   = blockIdx.x * 4 + w;
    const size_t ebase = (size_t)b * SL * NL;
    const int ca = 2 * l;
    const int cb = 2 * l + 1;
    const unsigned FULL = 0xffffffffu;
    const float LN2 = 0.6931471805599453f;
    const float L2E = 1.4426950408889634f;

    // packed constants for the vectorized exp2
    const u64 NEG1 = pack2(-1.0f, -1.0f);
    const u64 MAG2 = pack2(12582912.0f, 12582912.0f);
    const u64 P4   = pack2(0.0096181f, 0.0096181f);
    const u64 P3   = pack2(0.0555042f, 0.0555042f);
    const u64 P2   = pack2(0.2402265f, 0.2402265f);
    const u64 P1   = pack2(0.6931472f, 0.6931472f);
    const u64 ONE2 = pack2(1.0f, 1.0f);
    const u64 L2E2 = pack2(L2E, L2E);

    // E columns ca/cb, packed over adjacent row pairs (rows 2m, 2m+1).
    u64 Ea[32], Eb[32];
#pragma unroll
    for (int m = 0; m < 32; m++) {
        Ea[m] = pack2(__expf(trans[(2 * m) * NL + ca]),
                      __expf(trans[(2 * m + 1) * NL + ca]));
        Eb[m] = pack2(__expf(trans[(2 * m) * NL + cb]),
                      __expf(trans[(2 * m + 1) * NL + cb]));
    }
    const float fend_a = __expf(endt[ca]);
    const float fend_b = __expf(endt[cb]);

    // packed, log2-scaled emission load (8-byte aligned: ca is even)
#define LD2(T) mul2(*(const u64*)&emissions[ebase + (size_t)(T) * NL + ca], L2E2)

    // upfront prefetch: t=0..7 emissions + masks
    float2 e0  = *(const float2*)&emissions[ebase + (size_t)0 * NL + ca];
    u64 em1 = LD2(1);
    u64 em2 = LD2(2);
    u64 em3 = LD2(3);
    u64 eb0 = LD2(4);
    u64 eb1 = LD2(5);
    u64 eb2 = LD2(6);
    u64 eb3 = LD2(7);
    const int4 m0 = *(const int4*)&mask[b * SL];      // .y,.z,.w -> t=1,2,3
    int4 mv = *(const int4*)&mask[b * SL + 4];        // t=4..7

    // t = 0: normalize by score of label 0 -> q_0 = 1 exactly.
    float sc_a = startt[ca] + e0.x;
    float sc_b = startt[cb] + e0.y;
    const float z0 = __shfl_sync(FULL, sc_a, 0);
    float qa = __expf(sc_a - z0);
    float qb = __expf(sc_b - z0);
    float Z2 = z0 * L2E;                       // log2-domain accumulator
    *(float2*)&qbuf[w][0][ca] = make_float2(qa, qb);

    // C2_1 = e2_0^1 (q_0 = 1 -> n = 0)
    float C2;
    u64   C2p;
    {
        float nlo, nhi;
        unpack2(em1, nlo, nhi);
        C2  = __shfl_sync(FULL, nlo, 0);
        C2p = pack2(C2, C2);
    }

    // prologue: t = 1..3
    STEP(0, 1, em1, m0.y);  CUPD(em2);
    STEP(1, 0, em2, m0.z);  CUPD(em3);
    STEP(0, 1, em3, m0.w);  CUPD(eb0);

    // main loop: groups of 4, next group prefetched at group top (MLP=5)
#pragma unroll 1
    for (int t0 = 4; t0 < SL; t0 += 4) {
        const int tn0 = (t0 + 4 < SL) ? t0 + 4 : SL - 4;   // clamped reload;
        const u64 nb0 = LD2(tn0);                           // any scalar C2 is
        const u64 nb1 = LD2(tn0 + 1);                       // algebraically exact
        const u64 nb2 = LD2(tn0 + 2);
        const u64 nb3 = LD2(tn0 + 3);
        const int4 nmv = *(const int4*)&mask[b * SL + tn0];

        STEP(1, 0, eb0, mv.x);  CUPD(eb1);
        STEP(0, 1, eb1, mv.y);  CUPD(eb2);
        STEP(1, 0, eb2, mv.z);  CUPD(eb3);
        STEP(0, 1, eb3, mv.w);  CUPD(nb0);

        eb0 = nb0; eb1 = nb1; eb2 = nb2; eb3 = nb3; mv = nmv;
    }

    // out[b] = Z2*ln2 + ln( sum_j q_j * exp(end_j) )
    float v = qa * fend_a + qb * fend_b;
#pragma unroll
    for (int o = 16; o; o >>= 1) v += __shfl_xor_sync(FULL, v, o);
    if (l == 0) out[b] = fmaf(Z2, LN2, __logf(v));
#undef LD2
}

extern "C" void kernel_launch(void* const* d_in, const int* in_sizes, int n_in,
                              void* d_out, int out_size) {
    const float* emissions = (const float*)d_in[0];
    const int*   msk       = (const int*)d_in[1];
    const float* trans     = (const float*)d_in[2];
    const float* startt    = (const float*)d_in[3];
    const float* endt      = (const float*)d_in[4];
    crf_fwd_kernel<<<NB / 4, 128>>>(emissions, msk, trans, startt, endt, (float*)d_out);
}